// round 8
// baseline (speedup 1.0000x reference)
#include <cuda_runtime.h>
#include <math.h>

#define DM   768
#define NH   12
#define HD   64
#define DFF  3072
#define BB   2
#define SS   2048
#define RR   (BB*SS)      /* 4096 rows */
#define BHC  (BB*NH)      /* 24 head-batches */

// ---------------- scratch (device globals: allocation-guard safe) ----------
__device__ __align__(256) float g_ln1 [RR*DM];
__device__ __align__(256) float g_q   [RR*DM];
__device__ __align__(256) float g_kbuf[RR*DM];
__device__ __align__(256) float g_vbuf[RR*DM];
__device__ __align__(256) float g_attn[RR*DM];
__device__ __align__(256) float g_x1  [RR*DM];
__device__ __align__(256) float g_h2  [RR*DM];
__device__ __align__(256) float g_f1  [RR*DFF];
__device__ __align__(256) float g_sc  [(size_t)BHC*SS*SS];   // 402 MB scores
// tf32-rounded weight copies
__device__ __align__(256) float g_rwq [DM*DM];
__device__ __align__(256) float g_rwk [DM*DM];
__device__ __align__(256) float g_rwv [DM*DM];
__device__ __align__(256) float g_rwo [DM*DM];
__device__ __align__(256) float g_rw1 [DM*DFF];
__device__ __align__(256) float g_rw2 [DM*DFF];

// ---------------- tf32 helpers ---------------------------------------------
__device__ __forceinline__ unsigned f2tf_u(float f) {
    unsigned u;
    asm("cvt.rna.tf32.f32 %0, %1;" : "=r"(u) : "f"(f));
    return u;
}
__device__ __forceinline__ float f2tf(float f) { return __uint_as_float(f2tf_u(f)); }

__device__ __forceinline__ void mma8(float* c, const unsigned* a, const unsigned* b) {
    asm volatile(
        "mma.sync.aligned.m16n8k8.row.col.f32.tf32.tf32.f32 "
        "{%0,%1,%2,%3},{%4,%5,%6,%7},{%8,%9},{%0,%1,%2,%3};"
        : "+f"(c[0]), "+f"(c[1]), "+f"(c[2]), "+f"(c[3])
        : "r"(a[0]), "r"(a[1]), "r"(a[2]), "r"(a[3]), "r"(b[0]), "r"(b[1]));
}

// ---------------- weight pre-rounding ---------------------------------------
__global__ __launch_bounds__(256)
void round_tf32(const float* __restrict__ in, float* __restrict__ out, int n) {
    int i = blockIdx.x * 256 + threadIdx.x;
    if (i < n) out[i] = f2tf(in[i]);
}

// ---------------- layernorm (rounds output to tf32) -------------------------
__global__ __launch_bounds__(256)
void layernorm_kernel(const float* __restrict__ x,
                      const float* __restrict__ gamma,
                      const float* __restrict__ beta,
                      float* __restrict__ out) {
    int row = blockIdx.x;
    int tid = threadIdx.x;
    const float* xr = x + (size_t)row * DM;
    float v0 = xr[tid], v1 = xr[tid + 256], v2 = xr[tid + 512];

    __shared__ float red[256];
    red[tid] = v0 + v1 + v2;
    __syncthreads();
    #pragma unroll
    for (int o = 128; o > 0; o >>= 1) {
        if (tid < o) red[tid] += red[tid + o];
        __syncthreads();
    }
    float mu = red[0] * (1.0f / DM);
    __syncthreads();

    float d0 = v0 - mu, d1 = v1 - mu, d2 = v2 - mu;
    red[tid] = d0*d0 + d1*d1 + d2*d2;
    __syncthreads();
    #pragma unroll
    for (int o = 128; o > 0; o >>= 1) {
        if (tid < o) red[tid] += red[tid + o];
        __syncthreads();
    }
    float rstd = rsqrtf(red[0] * (1.0f / DM) + 1e-5f);

    float* orow = out + (size_t)row * DM;
    orow[tid]       = f2tf(d0 * rstd * gamma[tid]       + beta[tid]);
    orow[tid + 256] = f2tf(d1 * rstd * gamma[tid + 256] + beta[tid + 256]);
    orow[tid + 512] = f2tf(d2 * rstd * gamma[tid + 512] + beta[tid + 512]);
}

// ---------------- tf32 tensor-core GEMM NN, 128x128 tile, kstep 16 ---------
// EPI: 0=none, 1=+bias, 2=+bias+relu, 3=+bias+residual.  RND: round out to tf32
template<int EPI, bool RND>
__global__ __launch_bounds__(256)
void tgemm(const float* __restrict__ A, const float* __restrict__ B,
           float* __restrict__ C, const float* __restrict__ bias,
           const float* __restrict__ res, int M, int N, int K) {
    __shared__ float As[2][128][20];   // row-major m x k16, pad 20 (frag LDS conflict-free)
    __shared__ float Bs[2][16][136];   // row-major k16 x n, pad 136

    int tid = threadIdx.x, lane = tid & 31, warp = tid >> 5;
    int g = lane >> 2, t = lane & 3;
    int wm = (warp & 1) * 64, wn = (warp >> 1) * 32;
    int m0 = blockIdx.y * 128, n0 = blockIdx.x * 128;
    int ar = tid >> 1, ac = (tid & 1) * 8;   // A: 2 float4 per thread
    int br = tid >> 4, bc = (tid & 15) * 4;  // B: 2 float4 per thread

    const float* Ag = A + (size_t)(m0 + ar) * K + ac;
    const float* Bg = B + (size_t)br * N + n0 + bc;

    float4 pa0 = *(const float4*)(Ag);
    float4 pa1 = *(const float4*)(Ag + 4);
    float4 pb0 = *(const float4*)(Bg);
    float4 pb1 = *(const float4*)(Bg + 64);

    *(float4*)&As[0][ar][ac]     = pa0;
    *(float4*)&As[0][ar][ac + 4] = pa1;
    *(float4*)&Bs[0][br][bc]      = pb0;
    *(float4*)&Bs[0][br][bc + 64] = pb1;
    __syncthreads();

    float acc[16][4] = {};
    int nk = K >> 4;
    for (int s = 0; s < nk; s++) {
        int buf = s & 1;
        if (s + 1 < nk) {
            const float* Ag2 = Ag + (s + 1) * 16;
            const float* Bg2 = Bg + (size_t)(s + 1) * 16 * N;
            pa0 = *(const float4*)(Ag2);
            pa1 = *(const float4*)(Ag2 + 4);
            pb0 = *(const float4*)(Bg2);
            pb1 = *(const float4*)(Bg2 + 64);
        }
        #pragma unroll
        for (int kk = 0; kk < 16; kk += 8) {
            unsigned af[4][4], bf[4][2];
            #pragma unroll
            for (int i = 0; i < 4; i++) {
                int rb = wm + i * 16;
                af[i][0] = __float_as_uint(As[buf][rb + g]    [kk + t]);
                af[i][1] = __float_as_uint(As[buf][rb + g + 8][kk + t]);
                af[i][2] = __float_as_uint(As[buf][rb + g]    [kk + t + 4]);
                af[i][3] = __float_as_uint(As[buf][rb + g + 8][kk + t + 4]);
            }
            #pragma unroll
            for (int j = 0; j < 4; j++) {
                bf[j][0] = __float_as_uint(Bs[buf][kk + t]    [wn + j*8 + g]);
                bf[j][1] = __float_as_uint(Bs[buf][kk + t + 4][wn + j*8 + g]);
            }
            #pragma unroll
            for (int i = 0; i < 4; i++)
                #pragma unroll
                for (int j = 0; j < 4; j++)
                    mma8(acc[i*4 + j], af[i], bf[j]);
        }
        if (s + 1 < nk) {
            int nb = buf ^ 1;
            *(float4*)&As[nb][ar][ac]     = pa0;
            *(float4*)&As[nb][ar][ac + 4] = pa1;
            *(float4*)&Bs[nb][br][bc]      = pb0;
            *(float4*)&Bs[nb][br][bc + 64] = pb1;
        }
        __syncthreads();
    }

    #pragma unroll
    for (int i = 0; i < 4; i++) {
        int r = m0 + wm + i * 16 + g;
        #pragma unroll
        for (int j = 0; j < 4; j++) {
            int c = n0 + wn + j * 8 + 2 * t;
            float* a4 = acc[i*4 + j];
            float b0v = 0.f, b1v = 0.f;
            if (EPI >= 1) { b0v = bias[c]; b1v = bias[c + 1]; }
            float v0 = a4[0] + b0v, v1 = a4[1] + b1v;
            float v2 = a4[2] + b0v, v3 = a4[3] + b1v;
            if (EPI == 2) {
                v0 = fmaxf(v0, 0.f); v1 = fmaxf(v1, 0.f);
                v2 = fmaxf(v2, 0.f); v3 = fmaxf(v3, 0.f);
            }
            if (EPI == 3) {
                v0 += res[(size_t)r * N + c];       v1 += res[(size_t)r * N + c + 1];
                v2 += res[(size_t)(r+8) * N + c];   v3 += res[(size_t)(r+8) * N + c + 1];
            }
            if (RND) { v0 = f2tf(v0); v1 = f2tf(v1); v2 = f2tf(v2); v3 = f2tf(v3); }
            C[(size_t)r * N + c]         = v0;
            C[(size_t)r * N + c + 1]     = v1;
            C[(size_t)(r+8) * N + c]     = v2;
            C[(size_t)(r+8) * N + c + 1] = v3;
        }
    }
}

// ---------------- scores = Q @ K^T / 8 (tf32 NT, causal 128-tile skip) -----
__global__ __launch_bounds__(256)
void scores_tf(const float* __restrict__ Q, const float* __restrict__ Km) {
    int kt = blockIdx.x, qt = blockIdx.y;
    if (kt > qt) return;
    int bh = blockIdx.z, b = bh / NH, h = bh % NH;
    const float* Aq = Q  + (size_t)b * SS * DM + h * HD;
    const float* Bk = Km + (size_t)b * SS * DM + h * HD;
    float* Cs = g_sc + (size_t)bh * SS * SS;

    __shared__ float As[2][128][20];
    __shared__ float Bs[2][128][20];
    int tid = threadIdx.x, lane = tid & 31, warp = tid >> 5;
    int g = lane >> 2, t = lane & 3;
    int wm = (warp & 1) * 64, wn = (warp >> 1) * 32;
    int q0 = qt * 128, k0 = kt * 128;
    int ar = tid >> 1, ac = (tid & 1) * 8;

    const float* Ag = Aq + (size_t)(q0 + ar) * DM + ac;
    const float* Bg = Bk + (size_t)(k0 + ar) * DM + ac;

    float4 pa0 = *(const float4*)(Ag);
    float4 pa1 = *(const float4*)(Ag + 4);
    float4 pb0 = *(const float4*)(Bg);
    float4 pb1 = *(const float4*)(Bg + 4);

    *(float4*)&As[0][ar][ac]     = pa0;
    *(float4*)&As[0][ar][ac + 4] = pa1;
    *(float4*)&Bs[0][ar][ac]     = pb0;
    *(float4*)&Bs[0][ar][ac + 4] = pb1;
    __syncthreads();

    float acc[16][4] = {};
    #pragma unroll
    for (int s = 0; s < 4; s++) {          // K = 64 = 4 * 16
        int buf = s & 1;
        if (s < 3) {
            pa0 = *(const float4*)(Ag + (s + 1) * 16);
            pa1 = *(const float4*)(Ag + (s + 1) * 16 + 4);
            pb0 = *(const float4*)(Bg + (s + 1) * 16);
            pb1 = *(const float4*)(Bg + (s + 1) * 16 + 4);
        }
        #pragma unroll
        for (int kk = 0; kk < 16; kk += 8) {
            unsigned af[4][4], bf[4][2];
            #pragma unroll
            for (int i = 0; i < 4; i++) {
                int rb = wm + i * 16;
                af[i][0] = __float_as_uint(As[buf][rb + g]    [kk + t]);
                af[i][1] = __float_as_uint(As[buf][rb + g + 8][kk + t]);
                af[i][2] = __float_as_uint(As[buf][rb + g]    [kk + t + 4]);
                af[i][3] = __float_as_uint(As[buf][rb + g + 8][kk + t + 4]);
            }
            #pragma unroll
            for (int j = 0; j < 4; j++) {
                int nb = wn + j * 8;
                bf[j][0] = __float_as_uint(Bs[buf][nb + g][kk + t]);
                bf[j][1] = __float_as_uint(Bs[buf][nb + g][kk + t + 4]);
            }
            #pragma unroll
            for (int i = 0; i < 4; i++)
                #pragma unroll
                for (int j = 0; j < 4; j++)
                    mma8(acc[i*4 + j], af[i], bf[j]);
        }
        if (s < 3) {
            int nb = buf ^ 1;
            *(float4*)&As[nb][ar][ac]     = pa0;
            *(float4*)&As[nb][ar][ac + 4] = pa1;
            *(float4*)&Bs[nb][ar][ac]     = pb0;
            *(float4*)&Bs[nb][ar][ac + 4] = pb1;
        }
        __syncthreads();
    }

    #pragma unroll
    for (int i = 0; i < 4; i++) {
        int r = q0 + wm + i * 16 + g;
        #pragma unroll
        for (int j = 0; j < 4; j++) {
            int c = k0 + wn + j * 8 + 2 * t;
            float* a4 = acc[i*4 + j];
            Cs[(size_t)r * SS + c]         = a4[0] * 0.125f;
            Cs[(size_t)r * SS + c + 1]     = a4[1] * 0.125f;
            Cs[(size_t)(r+8) * SS + c]     = a4[2] * 0.125f;
            Cs[(size_t)(r+8) * SS + c + 1] = a4[3] * 0.125f;
        }
    }
}

// ---------------- causal softmax per row (rounds P to tf32) ----------------
__global__ __launch_bounds__(256)
void softmax_causal() {
    int q = blockIdx.x, bh = blockIdx.y;
    float* row = g_sc + (size_t)bh * SS * SS + (size_t)q * SS;
    int n  = q + 1;
    int nf = ((q >> 7) + 1) << 7;    // zero-fill to 128-aligned tile boundary
    int tid = threadIdx.x;

    __shared__ float buf[SS];
    __shared__ float red[256];

    float m = -1e30f;
    for (int i = tid; i < n; i += 256) { float v = row[i]; buf[i] = v; m = fmaxf(m, v); }
    red[tid] = m;
    __syncthreads();
    #pragma unroll
    for (int o = 128; o > 0; o >>= 1) {
        if (tid < o) red[tid] = fmaxf(red[tid], red[tid + o]);
        __syncthreads();
    }
    m = red[0];
    __syncthreads();

    float s = 0.0f;
    for (int i = tid; i < n; i += 256) { float e = __expf(buf[i] - m); buf[i] = e; s += e; }
    red[tid] = s;
    __syncthreads();
    #pragma unroll
    for (int o = 128; o > 0; o >>= 1) {
        if (tid < o) red[tid] += red[tid + o];
        __syncthreads();
    }
    float inv = 1.0f / red[0];

    for (int i = tid; i < n; i += 256)      row[i] = f2tf(buf[i] * inv);
    for (int i = n + tid; i < nf; i += 256) row[i] = 0.0f;
}

// ---------------- attn = P @ V (tf32, K clipped to causal extent) ----------
__global__ __launch_bounds__(256)
void attnv_tf(const float* __restrict__ V) {
    int qt = blockIdx.x, bh = blockIdx.y, b = bh / NH, h = bh % NH;
    const float* P  = g_sc   + (size_t)bh * SS * SS + (size_t)qt * 128 * SS;
    const float* Bv = V      + (size_t)b * SS * DM + h * HD;
    float*       C  = g_attn + (size_t)b * SS * DM + (size_t)qt * 128 * DM + h * HD;
    int nk = ((qt + 1) * 128) >> 4;

    __shared__ float As[2][128][20];
    __shared__ float Bs[2][16][72];
    int tid = threadIdx.x, lane = tid & 31, warp = tid >> 5;
    int g = lane >> 2, t = lane & 3;
    int wm = (warp & 3) * 32, wn = (warp >> 2) * 32;   // 4x2 warps, 32x32 each
    int ar = tid >> 1, ac = (tid & 1) * 8;
    int br = tid >> 4, bc = (tid & 15) * 4;

    const float* Ag = P  + (size_t)ar * SS + ac;
    const float* Bg = Bv + (size_t)br * DM + bc;

    float4 pa0 = *(const float4*)(Ag);
    float4 pa1 = *(const float4*)(Ag + 4);
    float4 pb0 = *(const float4*)(Bg);

    *(float4*)&As[0][ar][ac]     = pa0;
    *(float4*)&As[0][ar][ac + 4] = pa1;
    *(float4*)&Bs[0][br][bc]     = pb0;
    __syncthreads();

    float acc[8][4] = {};
    for (int s = 0; s < nk; s++) {
        int buf = s & 1;
        if (s + 1 < nk) {
            pa0 = *(const float4*)(Ag + (s + 1) * 16);
            pa1 = *(const float4*)(Ag + (s + 1) * 16 + 4);
            pb0 = *(const float4*)(Bg + (size_t)(s + 1) * 16 * DM);
        }
        #pragma unroll
        for (int kk = 0; kk < 16; kk += 8) {
            unsigned af[2][4], bf[4][2];
            #pragma unroll
            for (int i = 0; i < 2; i++) {
                int rb = wm + i * 16;
                af[i][0] = __float_as_uint(As[buf][rb + g]    [kk + t]);
                af[i][1] = __float_as_uint(As[buf][rb + g + 8][kk + t]);
                af[i][2] = __float_as_uint(As[buf][rb + g]    [kk + t + 4]);
                af[i][3] = __float_as_uint(As[buf][rb + g + 8][kk + t + 4]);
            }
            #pragma unroll
            for (int j = 0; j < 4; j++) {
                bf[j][0] = __float_as_uint(Bs[buf][kk + t]    [wn + j*8 + g]);
                bf[j][1] = __float_as_uint(Bs[buf][kk + t + 4][wn + j*8 + g]);
            }
            #pragma unroll
            for (int i = 0; i < 2; i++)
                #pragma unroll
                for (int j = 0; j < 4; j++)
                    mma8(acc[i*4 + j], af[i], bf[j]);
        }
        if (s + 1 < nk) {
            int nb = buf ^ 1;
            *(float4*)&As[nb][ar][ac]     = pa0;
            *(float4*)&As[nb][ar][ac + 4] = pa1;
            *(float4*)&Bs[nb][br][bc]     = pb0;
        }
        __syncthreads();
    }

    #pragma unroll
    for (int i = 0; i < 2; i++) {
        int r = wm + i * 16 + g;
        #pragma unroll
        for (int j = 0; j < 4; j++) {
            int c = wn + j * 8 + 2 * t;
            float* a4 = acc[i*4 + j];
            C[(size_t)r * DM + c]         = f2tf(a4[0]);
            C[(size_t)r * DM + c + 1]     = f2tf(a4[1]);
            C[(size_t)(r+8) * DM + c]     = f2tf(a4[2]);
            C[(size_t)(r+8) * DM + c + 1] = f2tf(a4[3]);
        }
    }
}

// ---------------- launch --------------------------------------------------
extern "C" void kernel_launch(void* const* d_in, const int* in_sizes, int n_in,
                              void* d_out, int out_size) {
    const float* x   = (const float*)d_in[0];
    const float* wq  = (const float*)d_in[1];
    const float* bq  = (const float*)d_in[2];
    const float* wk  = (const float*)d_in[3];
    const float* bk  = (const float*)d_in[4];
    const float* wv  = (const float*)d_in[5];
    const float* bv  = (const float*)d_in[6];
    const float* wo  = (const float*)d_in[7];
    const float* bo  = (const float*)d_in[8];
    const float* w1  = (const float*)d_in[9];
    const float* b1  = (const float*)d_in[10];
    const float* w2  = (const float*)d_in[11];
    const float* b2  = (const float*)d_in[12];
    const float* g1  = (const float*)d_in[13];
    const float* be1 = (const float*)d_in[14];
    const float* g2  = (const float*)d_in[15];
    const float* be2 = (const float*)d_in[16];
    float* out = (float*)d_out;

    float *ln1, *q, *k, *v, *attn, *x1, *h, *f1;
    float *rwq, *rwk, *rwv, *rwo, *rw1, *rw2;
    cudaGetSymbolAddress((void**)&ln1,  g_ln1);
    cudaGetSymbolAddress((void**)&q,    g_q);
    cudaGetSymbolAddress((void**)&k,    g_kbuf);
    cudaGetSymbolAddress((void**)&v,    g_vbuf);
    cudaGetSymbolAddress((void**)&attn, g_attn);
    cudaGetSymbolAddress((void**)&x1,   g_x1);
    cudaGetSymbolAddress((void**)&h,    g_h2);
    cudaGetSymbolAddress((void**)&f1,   g_f1);
    cudaGetSymbolAddress((void**)&rwq,  g_rwq);
    cudaGetSymbolAddress((void**)&rwk,  g_rwk);
    cudaGetSymbolAddress((void**)&rwv,  g_rwv);
    cudaGetSymbolAddress((void**)&rwo,  g_rwo);
    cudaGetSymbolAddress((void**)&rw1,  g_rw1);
    cudaGetSymbolAddress((void**)&rw2,  g_rw2);

    // pre-round weights to tf32 (so the GEMM hot loop needs no conversion)
    round_tf32<<<(DM*DM + 255)/256, 256>>>(wq, rwq, DM*DM);
    round_tf32<<<(DM*DM + 255)/256, 256>>>(wk, rwk, DM*DM);
    round_tf32<<<(DM*DM + 255)/256, 256>>>(wv, rwv, DM*DM);
    round_tf32<<<(DM*DM + 255)/256, 256>>>(wo, rwo, DM*DM);
    round_tf32<<<(DM*DFF + 255)/256, 256>>>(w1, rw1, DM*DFF);
    round_tf32<<<(DM*DFF + 255)/256, 256>>>(w2, rw2, DM*DFF);

    // x -> ln1 (rounded)
    layernorm_kernel<<<RR, 256>>>(x, g1, be1, ln1);
    // q,k,v = ln1 @ w{q,k,v} + b  (rounded: feed scores / attnv MMAs)
    tgemm<1, true><<<dim3(DM/128, RR/128), 256>>>(ln1, rwq, q, bq, nullptr, RR, DM, DM);
    tgemm<1, true><<<dim3(DM/128, RR/128), 256>>>(ln1, rwk, k, bk, nullptr, RR, DM, DM);
    tgemm<1, true><<<dim3(DM/128, RR/128), 256>>>(ln1, rwv, v, bv, nullptr, RR, DM, DM);
    // scores = QK^T/8 (causal tiles only)
    scores_tf<<<dim3(SS/128, SS/128, BHC), 256>>>(q, k);
    // causal softmax in place (rounds P)
    softmax_causal<<<dim3(SS, BHC), 256>>>();
    // attn = P @ V (rounded)
    attnv_tf<<<dim3(SS/128, BHC), 256>>>(v);
    // x1 = attn @ wo + bo + x   (residual 1, full fp32)
    tgemm<3, false><<<dim3(DM/128, RR/128), 256>>>(attn, rwo, x1, bo, x, RR, DM, DM);
    // h = ln(x1) (rounded)
    layernorm_kernel<<<RR, 256>>>(x1, g2, be2, h);
    // f1 = relu(h @ w1 + b1) (rounded)
    tgemm<2, true><<<dim3(DFF/128, RR/128), 256>>>(h, rw1, f1, b1, nullptr, RR, DFF, DM);
    // out = f1 @ w2 + b2 + x1   (residual 2, full fp32)
    tgemm<3, false><<<dim3(DM/128, RR/128), 256>>>(f1, rw2, out, b2, x1, RR, DM, DFF);
}

// round 9
// speedup vs baseline: 1.0022x; 1.0022x over previous
#include <cuda_runtime.h>
#include <math.h>

#define DM   768
#define NH   12
#define HD   64
#define DFF  3072
#define BB   2
#define SS   2048
#define RR   (BB*SS)      /* 4096 rows */
#define BHC  (BB*NH)      /* 24 head-batches */

// ---------------- scratch (device globals: allocation-guard safe) ----------
__device__ __align__(256) float g_ln1 [RR*DM];
__device__ __align__(256) float g_q   [RR*DM];
__device__ __align__(256) float g_kbuf[RR*DM];
__device__ __align__(256) float g_vbuf[RR*DM];
__device__ __align__(256) float g_attn[RR*DM];
__device__ __align__(256) float g_x1  [RR*DM];
__device__ __align__(256) float g_h2  [RR*DM];
__device__ __align__(256) float g_f1  [RR*DFF];
__device__ __align__(256) float g_sc  [(size_t)BHC*SS*SS];   // 402 MB scores
// tf32-rounded weight copies
__device__ __align__(256) float g_rwq [DM*DM];
__device__ __align__(256) float g_rwk [DM*DM];
__device__ __align__(256) float g_rwv [DM*DM];
__device__ __align__(256) float g_rwo [DM*DM];
__device__ __align__(256) float g_rw1 [DM*DFF];
__device__ __align__(256) float g_rw2 [DM*DFF];

// ---------------- tf32 helpers ---------------------------------------------
__device__ __forceinline__ unsigned f2tf_u(float f) {
    unsigned u;
    asm("cvt.rna.tf32.f32 %0, %1;" : "=r"(u) : "f"(f));
    return u;
}
__device__ __forceinline__ float f2tf(float f) { return __uint_as_float(f2tf_u(f)); }

__device__ __forceinline__ void mma8(float* c, const unsigned* a, const unsigned* b) {
    asm volatile(
        "mma.sync.aligned.m16n8k8.row.col.f32.tf32.tf32.f32 "
        "{%0,%1,%2,%3},{%4,%5,%6,%7},{%8,%9},{%0,%1,%2,%3};"
        : "+f"(c[0]), "+f"(c[1]), "+f"(c[2]), "+f"(c[3])
        : "r"(a[0]), "r"(a[1]), "r"(a[2]), "r"(a[3]), "r"(b[0]), "r"(b[1]));
}

// ---------------- weight pre-rounding ---------------------------------------
__global__ __launch_bounds__(256)
void round_tf32(const float* __restrict__ in, float* __restrict__ out, int n) {
    int i = blockIdx.x * 256 + threadIdx.x;
    if (i < n) out[i] = f2tf(in[i]);
}

// ---------------- layernorm (rounds output to tf32) -------------------------
__global__ __launch_bounds__(256)
void layernorm_kernel(const float* __restrict__ x,
                      const float* __restrict__ gamma,
                      const float* __restrict__ beta,
                      float* __restrict__ out) {
    int row = blockIdx.x;
    int tid = threadIdx.x;
    const float* xr = x + (size_t)row * DM;
    float v0 = xr[tid], v1 = xr[tid + 256], v2 = xr[tid + 512];

    __shared__ float red[256];
    red[tid] = v0 + v1 + v2;
    __syncthreads();
    #pragma unroll
    for (int o = 128; o > 0; o >>= 1) {
        if (tid < o) red[tid] += red[tid + o];
        __syncthreads();
    }
    float mu = red[0] * (1.0f / DM);
    __syncthreads();

    float d0 = v0 - mu, d1 = v1 - mu, d2 = v2 - mu;
    red[tid] = d0*d0 + d1*d1 + d2*d2;
    __syncthreads();
    #pragma unroll
    for (int o = 128; o > 0; o >>= 1) {
        if (tid < o) red[tid] += red[tid + o];
        __syncthreads();
    }
    float rstd = rsqrtf(red[0] * (1.0f / DM) + 1e-5f);

    float* orow = out + (size_t)row * DM;
    orow[tid]       = f2tf(d0 * rstd * gamma[tid]       + beta[tid]);
    orow[tid + 256] = f2tf(d1 * rstd * gamma[tid + 256] + beta[tid + 256]);
    orow[tid + 512] = f2tf(d2 * rstd * gamma[tid + 512] + beta[tid + 512]);
}

// ---------------- tf32 tensor-core GEMM NN, 128x128 tile, kstep 16 ---------
// EPI: 0=none, 1=+bias, 2=+bias+relu, 3=+bias+residual.  RND: round out to tf32
template<int EPI, bool RND>
__global__ __launch_bounds__(256)
void tgemm(const float* __restrict__ A, const float* __restrict__ B,
           float* __restrict__ C, const float* __restrict__ bias,
           const float* __restrict__ res, int M, int N, int K) {
    __shared__ float As[2][128][20];   // row-major m x k16, pad 20 (frag LDS conflict-free)
    __shared__ float Bs[2][16][136];   // row-major k16 x n, pad 136

    int tid = threadIdx.x, lane = tid & 31, warp = tid >> 5;
    int g = lane >> 2, t = lane & 3;
    int wm = (warp & 1) * 64, wn = (warp >> 1) * 32;
    int m0 = blockIdx.y * 128, n0 = blockIdx.x * 128;
    int ar = tid >> 1, ac = (tid & 1) * 8;   // A: 2 float4 per thread
    int br = tid >> 4, bc = (tid & 15) * 4;  // B: 2 float4 per thread

    const float* Ag = A + (size_t)(m0 + ar) * K + ac;
    const float* Bg = B + (size_t)br * N + n0 + bc;

    float4 pa0 = *(const float4*)(Ag);
    float4 pa1 = *(const float4*)(Ag + 4);
    float4 pb0 = *(const float4*)(Bg);
    float4 pb1 = *(const float4*)(Bg + 64);

    *(float4*)&As[0][ar][ac]     = pa0;
    *(float4*)&As[0][ar][ac + 4] = pa1;
    *(float4*)&Bs[0][br][bc]      = pb0;
    *(float4*)&Bs[0][br][bc + 64] = pb1;
    __syncthreads();

    float acc[16][4] = {};
    int nk = K >> 4;
    for (int s = 0; s < nk; s++) {
        int buf = s & 1;
        if (s + 1 < nk) {
            const float* Ag2 = Ag + (s + 1) * 16;
            const float* Bg2 = Bg + (size_t)(s + 1) * 16 * N;
            pa0 = *(const float4*)(Ag2);
            pa1 = *(const float4*)(Ag2 + 4);
            pb0 = *(const float4*)(Bg2);
            pb1 = *(const float4*)(Bg2 + 64);
        }
        #pragma unroll
        for (int kk = 0; kk < 16; kk += 8) {
            unsigned af[4][4], bf[4][2];
            #pragma unroll
            for (int i = 0; i < 4; i++) {
                int rb = wm + i * 16;
                af[i][0] = __float_as_uint(As[buf][rb + g]    [kk + t]);
                af[i][1] = __float_as_uint(As[buf][rb + g + 8][kk + t]);
                af[i][2] = __float_as_uint(As[buf][rb + g]    [kk + t + 4]);
                af[i][3] = __float_as_uint(As[buf][rb + g + 8][kk + t + 4]);
            }
            #pragma unroll
            for (int j = 0; j < 4; j++) {
                bf[j][0] = __float_as_uint(Bs[buf][kk + t]    [wn + j*8 + g]);
                bf[j][1] = __float_as_uint(Bs[buf][kk + t + 4][wn + j*8 + g]);
            }
            #pragma unroll
            for (int i = 0; i < 4; i++)
                #pragma unroll
                for (int j = 0; j < 4; j++)
                    mma8(acc[i*4 + j], af[i], bf[j]);
        }
        if (s + 1 < nk) {
            int nb = buf ^ 1;
            *(float4*)&As[nb][ar][ac]     = pa0;
            *(float4*)&As[nb][ar][ac + 4] = pa1;
            *(float4*)&Bs[nb][br][bc]      = pb0;
            *(float4*)&Bs[nb][br][bc + 64] = pb1;
        }
        __syncthreads();
    }

    #pragma unroll
    for (int i = 0; i < 4; i++) {
        int r = m0 + wm + i * 16 + g;
        #pragma unroll
        for (int j = 0; j < 4; j++) {
            int c = n0 + wn + j * 8 + 2 * t;
            float* a4 = acc[i*4 + j];
            float b0v = 0.f, b1v = 0.f;
            if (EPI >= 1) { b0v = bias[c]; b1v = bias[c + 1]; }
            float v0 = a4[0] + b0v, v1 = a4[1] + b1v;
            float v2 = a4[2] + b0v, v3 = a4[3] + b1v;
            if (EPI == 2) {
                v0 = fmaxf(v0, 0.f); v1 = fmaxf(v1, 0.f);
                v2 = fmaxf(v2, 0.f); v3 = fmaxf(v3, 0.f);
            }
            if (EPI == 3) {
                v0 += res[(size_t)r * N + c];       v1 += res[(size_t)r * N + c + 1];
                v2 += res[(size_t)(r+8) * N + c];   v3 += res[(size_t)(r+8) * N + c + 1];
            }
            if (RND) { v0 = f2tf(v0); v1 = f2tf(v1); v2 = f2tf(v2); v3 = f2tf(v3); }
            C[(size_t)r * N + c]         = v0;
            C[(size_t)r * N + c + 1]     = v1;
            C[(size_t)(r+8) * N + c]     = v2;
            C[(size_t)(r+8) * N + c + 1] = v3;
        }
    }
}

// ---------------- scores = Q @ K^T / 8 (tf32 NT, causal 128-tile skip) -----
__global__ __launch_bounds__(256)
void scores_tf(const float* __restrict__ Q, const float* __restrict__ Km) {
    int kt = blockIdx.x, qt = blockIdx.y;
    if (kt > qt) return;
    int bh = blockIdx.z, b = bh / NH, h = bh % NH;
    const float* Aq = Q  + (size_t)b * SS * DM + h * HD;
    const float* Bk = Km + (size_t)b * SS * DM + h * HD;
    float* Cs = g_sc + (size_t)bh * SS * SS;

    __shared__ float As[2][128][20];
    __shared__ float Bs[2][128][20];
    int tid = threadIdx.x, lane = tid & 31, warp = tid >> 5;
    int g = lane >> 2, t = lane & 3;
    int wm = (warp & 1) * 64, wn = (warp >> 1) * 32;
    int q0 = qt * 128, k0 = kt * 128;
    int ar = tid >> 1, ac = (tid & 1) * 8;

    const float* Ag = Aq + (size_t)(q0 + ar) * DM + ac;
    const float* Bg = Bk + (size_t)(k0 + ar) * DM + ac;

    float4 pa0 = *(const float4*)(Ag);
    float4 pa1 = *(const float4*)(Ag + 4);
    float4 pb0 = *(const float4*)(Bg);
    float4 pb1 = *(const float4*)(Bg + 4);

    *(float4*)&As[0][ar][ac]     = pa0;
    *(float4*)&As[0][ar][ac + 4] = pa1;
    *(float4*)&Bs[0][ar][ac]     = pb0;
    *(float4*)&Bs[0][ar][ac + 4] = pb1;
    __syncthreads();

    float acc[16][4] = {};
    #pragma unroll
    for (int s = 0; s < 4; s++) {          // K = 64 = 4 * 16
        int buf = s & 1;
        if (s < 3) {
            pa0 = *(const float4*)(Ag + (s + 1) * 16);
            pa1 = *(const float4*)(Ag + (s + 1) * 16 + 4);
            pb0 = *(const float4*)(Bg + (s + 1) * 16);
            pb1 = *(const float4*)(Bg + (s + 1) * 16 + 4);
        }
        #pragma unroll
        for (int kk = 0; kk < 16; kk += 8) {
            unsigned af[4][4], bf[4][2];
            #pragma unroll
            for (int i = 0; i < 4; i++) {
                int rb = wm + i * 16;
                af[i][0] = __float_as_uint(As[buf][rb + g]    [kk + t]);
                af[i][1] = __float_as_uint(As[buf][rb + g + 8][kk + t]);
                af[i][2] = __float_as_uint(As[buf][rb + g]    [kk + t + 4]);
                af[i][3] = __float_as_uint(As[buf][rb + g + 8][kk + t + 4]);
            }
            #pragma unroll
            for (int j = 0; j < 4; j++) {
                int nb = wn + j * 8;
                bf[j][0] = __float_as_uint(Bs[buf][nb + g][kk + t]);
                bf[j][1] = __float_as_uint(Bs[buf][nb + g][kk + t + 4]);
            }
            #pragma unroll
            for (int i = 0; i < 4; i++)
                #pragma unroll
                for (int j = 0; j < 4; j++)
                    mma8(acc[i*4 + j], af[i], bf[j]);
        }
        if (s < 3) {
            int nb = buf ^ 1;
            *(float4*)&As[nb][ar][ac]     = pa0;
            *(float4*)&As[nb][ar][ac + 4] = pa1;
            *(float4*)&Bs[nb][ar][ac]     = pb0;
            *(float4*)&Bs[nb][ar][ac + 4] = pb1;
        }
        __syncthreads();
    }

    #pragma unroll
    for (int i = 0; i < 4; i++) {
        int r = q0 + wm + i * 16 + g;
        #pragma unroll
        for (int j = 0; j < 4; j++) {
            int c = k0 + wn + j * 8 + 2 * t;
            float* a4 = acc[i*4 + j];
            Cs[(size_t)r * SS + c]         = a4[0] * 0.125f;
            Cs[(size_t)r * SS + c + 1]     = a4[1] * 0.125f;
            Cs[(size_t)(r+8) * SS + c]     = a4[2] * 0.125f;
            Cs[(size_t)(r+8) * SS + c + 1] = a4[3] * 0.125f;
        }
    }
}

// ---------------- causal softmax per row (rounds P to tf32) ----------------
__global__ __launch_bounds__(256)
void softmax_causal() {
    int q = blockIdx.x, bh = blockIdx.y;
    float* row = g_sc + (size_t)bh * SS * SS + (size_t)q * SS;
    int n  = q + 1;
    int nf = ((q >> 7) + 1) << 7;    // zero-fill to 128-aligned tile boundary
    int tid = threadIdx.x;

    __shared__ float buf[SS];
    __shared__ float red[256];

    float m = -1e30f;
    for (int i = tid; i < n; i += 256) { float v = row[i]; buf[i] = v; m = fmaxf(m, v); }
    red[tid] = m;
    __syncthreads();
    #pragma unroll
    for (int o = 128; o > 0; o >>= 1) {
        if (tid < o) red[tid] = fmaxf(red[tid], red[tid + o]);
        __syncthreads();
    }
    m = red[0];
    __syncthreads();

    float s = 0.0f;
    for (int i = tid; i < n; i += 256) { float e = __expf(buf[i] - m); buf[i] = e; s += e; }
    red[tid] = s;
    __syncthreads();
    #pragma unroll
    for (int o = 128; o > 0; o >>= 1) {
        if (tid < o) red[tid] += red[tid + o];
        __syncthreads();
    }
    float inv = 1.0f / red[0];

    for (int i = tid; i < n; i += 256)      row[i] = f2tf(buf[i] * inv);
    for (int i = n + tid; i < nf; i += 256) row[i] = 0.0f;
}

// ---------------- attn = P @ V (tf32, K clipped to causal extent) ----------
__global__ __launch_bounds__(256)
void attnv_tf(const float* __restrict__ V) {
    int qt = blockIdx.x, bh = blockIdx.y, b = bh / NH, h = bh % NH;
    const float* P  = g_sc   + (size_t)bh * SS * SS + (size_t)qt * 128 * SS;
    const float* Bv = V      + (size_t)b * SS * DM + h * HD;
    float*       C  = g_attn + (size_t)b * SS * DM + (size_t)qt * 128 * DM + h * HD;
    int nk = ((qt + 1) * 128) >> 4;

    __shared__ float As[2][128][20];
    __shared__ float Bs[2][16][72];
    int tid = threadIdx.x, lane = tid & 31, warp = tid >> 5;
    int g = lane >> 2, t = lane & 3;
    int wm = (warp & 3) * 32, wn = (warp >> 2) * 32;   // 4x2 warps, 32x32 each
    int ar = tid >> 1, ac = (tid & 1) * 8;
    int br = tid >> 4, bc = (tid & 15) * 4;

    const float* Ag = P  + (size_t)ar * SS + ac;
    const float* Bg = Bv + (size_t)br * DM + bc;

    float4 pa0 = *(const float4*)(Ag);
    float4 pa1 = *(const float4*)(Ag + 4);
    float4 pb0 = *(const float4*)(Bg);

    *(float4*)&As[0][ar][ac]     = pa0;
    *(float4*)&As[0][ar][ac + 4] = pa1;
    *(float4*)&Bs[0][br][bc]     = pb0;
    __syncthreads();

    float acc[8][4] = {};
    for (int s = 0; s < nk; s++) {
        int buf = s & 1;
        if (s + 1 < nk) {
            pa0 = *(const float4*)(Ag + (s + 1) * 16);
            pa1 = *(const float4*)(Ag + (s + 1) * 16 + 4);
            pb0 = *(const float4*)(Bg + (size_t)(s + 1) * 16 * DM);
        }
        #pragma unroll
        for (int kk = 0; kk < 16; kk += 8) {
            unsigned af[2][4], bf[4][2];
            #pragma unroll
            for (int i = 0; i < 2; i++) {
                int rb = wm + i * 16;
                af[i][0] = __float_as_uint(As[buf][rb + g]    [kk + t]);
                af[i][1] = __float_as_uint(As[buf][rb + g + 8][kk + t]);
                af[i][2] = __float_as_uint(As[buf][rb + g]    [kk + t + 4]);
                af[i][3] = __float_as_uint(As[buf][rb + g + 8][kk + t + 4]);
            }
            #pragma unroll
            for (int j = 0; j < 4; j++) {
                bf[j][0] = __float_as_uint(Bs[buf][kk + t]    [wn + j*8 + g]);
                bf[j][1] = __float_as_uint(Bs[buf][kk + t + 4][wn + j*8 + g]);
            }
            #pragma unroll
            for (int i = 0; i < 2; i++)
                #pragma unroll
                for (int j = 0; j < 4; j++)
                    mma8(acc[i*4 + j], af[i], bf[j]);
        }
        if (s + 1 < nk) {
            int nb = buf ^ 1;
            *(float4*)&As[nb][ar][ac]     = pa0;
            *(float4*)&As[nb][ar][ac + 4] = pa1;
            *(float4*)&Bs[nb][br][bc]     = pb0;
        }
        __syncthreads();
    }

    #pragma unroll
    for (int i = 0; i < 2; i++) {
        int r = wm + i * 16 + g;
        #pragma unroll
        for (int j = 0; j < 4; j++) {
            int c = wn + j * 8 + 2 * t;
            float* a4 = acc[i*4 + j];
            C[(size_t)r * DM + c]         = f2tf(a4[0]);
            C[(size_t)r * DM + c + 1]     = f2tf(a4[1]);
            C[(size_t)(r+8) * DM + c]     = f2tf(a4[2]);
            C[(size_t)(r+8) * DM + c + 1] = f2tf(a4[3]);
        }
    }
}

// ---------------- launch --------------------------------------------------
extern "C" void kernel_launch(void* const* d_in, const int* in_sizes, int n_in,
                              void* d_out, int out_size) {
    const float* x   = (const float*)d_in[0];
    const float* wq  = (const float*)d_in[1];
    const float* bq  = (const float*)d_in[2];
    const float* wk  = (const float*)d_in[3];
    const float* bk  = (const float*)d_in[4];
    const float* wv  = (const float*)d_in[5];
    const float* bv  = (const float*)d_in[6];
    const float* wo  = (const float*)d_in[7];
    const float* bo  = (const float*)d_in[8];
    const float* w1  = (const float*)d_in[9];
    const float* b1  = (const float*)d_in[10];
    const float* w2  = (const float*)d_in[11];
    const float* b2  = (const float*)d_in[12];
    const float* g1  = (const float*)d_in[13];
    const float* be1 = (const float*)d_in[14];
    const float* g2  = (const float*)d_in[15];
    const float* be2 = (const float*)d_in[16];
    float* out = (float*)d_out;

    float *ln1, *q, *k, *v, *attn, *x1, *h, *f1;
    float *rwq, *rwk, *rwv, *rwo, *rw1, *rw2;
    cudaGetSymbolAddress((void**)&ln1,  g_ln1);
    cudaGetSymbolAddress((void**)&q,    g_q);
    cudaGetSymbolAddress((void**)&k,    g_kbuf);
    cudaGetSymbolAddress((void**)&v,    g_vbuf);
    cudaGetSymbolAddress((void**)&attn, g_attn);
    cudaGetSymbolAddress((void**)&x1,   g_x1);
    cudaGetSymbolAddress((void**)&h,    g_h2);
    cudaGetSymbolAddress((void**)&f1,   g_f1);
    cudaGetSymbolAddress((void**)&rwq,  g_rwq);
    cudaGetSymbolAddress((void**)&rwk,  g_rwk);
    cudaGetSymbolAddress((void**)&rwv,  g_rwv);
    cudaGetSymbolAddress((void**)&rwo,  g_rwo);
    cudaGetSymbolAddress((void**)&rw1,  g_rw1);
    cudaGetSymbolAddress((void**)&rw2,  g_rw2);

    // pre-round weights to tf32 (so the GEMM hot loop needs no conversion)
    round_tf32<<<(DM*DM + 255)/256, 256>>>(wq, rwq, DM*DM);
    round_tf32<<<(DM*DM + 255)/256, 256>>>(wk, rwk, DM*DM);
    round_tf32<<<(DM*DM + 255)/256, 256>>>(wv, rwv, DM*DM);
    round_tf32<<<(DM*DM + 255)/256, 256>>>(wo, rwo, DM*DM);
    round_tf32<<<(DM*DFF + 255)/256, 256>>>(w1, rw1, DM*DFF);
    round_tf32<<<(DM*DFF + 255)/256, 256>>>(w2, rw2, DM*DFF);

    // x -> ln1 (rounded)
    layernorm_kernel<<<RR, 256>>>(x, g1, be1, ln1);
    // q,k,v = ln1 @ w{q,k,v} + b  (rounded: feed scores / attnv MMAs)
    tgemm<1, true><<<dim3(DM/128, RR/128), 256>>>(ln1, rwq, q, bq, nullptr, RR, DM, DM);
    tgemm<1, true><<<dim3(DM/128, RR/128), 256>>>(ln1, rwk, k, bk, nullptr, RR, DM, DM);
    tgemm<1, true><<<dim3(DM/128, RR/128), 256>>>(ln1, rwv, v, bv, nullptr, RR, DM, DM);
    // scores = QK^T/8 (causal tiles only)
    scores_tf<<<dim3(SS/128, SS/128, BHC), 256>>>(q, k);
    // causal softmax in place (rounds P)
    softmax_causal<<<dim3(SS, BHC), 256>>>();
    // attn = P @ V (rounded)
    attnv_tf<<<dim3(SS/128, BHC), 256>>>(v);
    // x1 = attn @ wo + bo + x   (residual 1, full fp32)
    tgemm<3, false><<<dim3(DM/128, RR/128), 256>>>(attn, rwo, x1, bo, x, RR, DM, DM);
    // h = ln(x1) (rounded)
    layernorm_kernel<<<RR, 256>>>(x1, g2, be2, h);
    // f1 = relu(h @ w1 + b1) (rounded)
    tgemm<2, true><<<dim3(DFF/128, RR/128), 256>>>(h, rw1, f1, b1, nullptr, RR, DFF, DM);
    // out = f1 @ w2 + b2 + x1   (residual 2, full fp32)
    tgemm<3, false><<<dim3(DM/128, RR/128), 256>>>(f1, rw2, out, b2, x1, RR, DM, DFF);
}